// round 8
// baseline (speedup 1.0000x reference)
#include <cuda_runtime.h>
#include <math_constants.h>
#include <cstdint>

typedef unsigned long long ULL;

#define Bc 1024
#define Sc 2048
#define Hc 50
#define TT 128
#define NTILE 16
#define NTH 256
#define RS 60
#define L2E 1.4426950408889634f

// ---- dynamic SMEM layout (bytes), total 75264 -> 3 CTAs/SM ----
#define OFF_BUF0  0                 // float[128*60] 30720
#define OFF_BUF1  30720             // float[128*60] 30720
#define OFF_BFRAG 61440             // u32[7*448]    12544
#define OFF_WS    73984             // float[64]       256
#define OFF_SPART 74240             // float[2*128]   1024
#define SMEM_BYTES 75264
#define OFF_PPV   OFF_SPART         // overlay: setup only
#define OFF_SCTX  0                 // overlay buf0: post-loop only
#define OFF_SL    1600

__device__ __forceinline__ uint32_t smem_u32(const void* p) {
    uint32_t a;
    asm("{ .reg .u64 t; cvta.to.shared.u64 t, %1; cvt.u32.u64 %0, t; }" : "=r"(a) : "l"(p));
    return a;
}
__device__ __forceinline__ float fast_ex2(float x) {
    float r; asm("ex2.approx.f32 %0, %1;" : "=f"(r) : "f"(x)); return r;
}
__device__ __forceinline__ float fast_tanh(float x) {
    float r; asm("tanh.approx.f32 %0, %1;" : "=f"(r) : "f"(x)); return r;
}
__device__ __forceinline__ ULL pack2(float lo, float hi) {
    ULL r; asm("mov.b64 %0, {%1, %2};" : "=l"(r) : "f"(lo), "f"(hi)); return r;
}
__device__ __forceinline__ void unpack2(ULL v, float& lo, float& hi) {
    asm("mov.b64 {%0, %1}, %2;" : "=f"(lo), "=f"(hi) : "l"(v));
}
#define FMA2(d, a, b) asm("fma.rn.f32x2 %0, %1, %2, %0;" : "+l"(d) : "l"(a), "l"(b))
__device__ __forceinline__ uint32_t to_tf32(float v) {
    uint32_t u; asm("cvt.rna.tf32.f32 %0, %1;" : "=r"(u) : "f"(v)); return u;
}

#define MMA_TF32(C, A, B0, B1)                                                  \
    asm("mma.sync.aligned.m16n8k8.row.col.f32.tf32.tf32.f32 "                   \
        "{%0,%1,%2,%3}, {%4,%5,%6,%7}, {%8,%9}, {%0,%1,%2,%3};"                 \
        : "+f"((C)[0]), "+f"((C)[1]), "+f"((C)[2]), "+f"((C)[3])                \
        : "r"((A)[0]), "r"((A)[1]), "r"((A)[2]), "r"((A)[3]), "r"(B0), "r"(B1))

#define CP_ASYNC8(dst, src) \
    asm volatile("cp.async.ca.shared.global [%0], [%1], 8;" :: "r"(dst), "l"(src))
#define CP_COMMIT() asm volatile("cp.async.commit_group;" ::: "memory")
#define CP_WAIT1()  asm volatile("cp.async.wait_group 1;" ::: "memory")

__global__ __launch_bounds__(NTH, 3)
void additive_attn_kernel(const float* __restrict__ dec,
                          const float* __restrict__ enc,     // (S,B,H)
                          const int*   __restrict__ mask,    // (B,S)
                          const float* __restrict__ Wp,
                          const float* __restrict__ We,
                          const float* __restrict__ Ws,
                          float* __restrict__ out)
{
    extern __shared__ __align__(16) char smem[];
    const uint32_t smb = smem_u32(smem);
    uint32_t* bfrag = (uint32_t*)(smem + OFF_BFRAG);
    float* ws    = (float*)(smem + OFF_WS);
    float* ppv   = (float*)(smem + OFF_PPV);
    float* spart = (float*)(smem + OFF_SPART);

    const int b    = blockIdx.x;
    const int tid  = threadIdx.x;
    const int lane = tid & 31;
    const int wid  = tid >> 5;
    const int g    = lane >> 2;
    const int c    = lane & 3;
    const int wr   = wid & 3;      // token block (32 tokens)
    const int wc   = wid >> 2;     // n half (0: n 0-31, 1: n 32-55)

    // ---- setup: pp, ws ----
    if (tid < 64) {
        float pp = 0.0f;
        if (tid < Hc) {
            #pragma unroll
            for (int k = 0; k < Hc; k++)
                pp = fmaf(Wp[tid * Hc + k], dec[b * Hc + k], pp);
        }
        ppv[tid] = pp;
        ws[tid]  = (tid < Hc) ? Ws[tid] : 0.0f;
    }
    __syncthreads();

    // ---- build B fragments: per k-step 448 u32 = pairs(0,1)(2,3)(4,5) + nb6 ----
    for (int i = tid; i < 7 * 448; i += NTH) {
        int s   = i / 448;
        int rem = i - s * 448;
        int ln, r, nb;
        if (rem < 384) {
            int p    = rem >> 7;
            int rem2 = rem & 127;
            ln = rem2 >> 2;
            int q = rem2 & 3;
            nb = 2 * p + (q >> 1);
            r  = q & 1;
        } else {
            int rem2 = rem - 384;
            ln = rem2 >> 1;
            r  = rem2 & 1;
            nb = 6;
        }
        int k = 8 * s + (ln & 3) + 4 * r;
        int n = nb * 8 + (ln >> 2);
        float v = 0.0f;
        if (n < Hc) {
            if (k < Hc)       v = We[n * Hc + k];
            else if (k == 50) v = ppv[n];
        }
        bfrag[i] = to_tf32(v);
    }
    __syncthreads();   // ppv consumed; spart region free

    // ---- ws to regs ----
    float wsr[4][2];
    #pragma unroll
    for (int nb = 0; nb < 4; nb++) {
        wsr[nb][0] = ws[wc * 32 + nb * 8 + 2 * c];
        wsr[nb][1] = ws[wc * 32 + nb * 8 + 2 * c + 1];
    }

    // ---- pad cols 50..59 in BOTH buffers ----
    for (int i = tid; i < TT * 10; i += NTH) {
        int t = i / 10, cc = i - 10 * (i / 10);
        float v = (cc == 0) ? 1.0f : 0.0f;          // col 50 = 1.0 (pp lane)
        ((float*)(smem + OFF_BUF0))[t * RS + 50 + cc] = v;
        ((float*)(smem + OFF_BUF1))[t * RS + 50 + cc] = v;
    }

    // ---- staging geometry: lane = 8B chunk (0..24), token = wid + 8i ----
    const float* encb = enc + (size_t)b * Hc;
    const bool st_on = (lane < 25);
    const size_t tok_stride = (size_t)(Bc * Hc);
    const uint32_t d_off = (uint32_t)(wid * RS + 2 * lane) * 4u;
    const size_t  s_off = (size_t)wid * tok_stride + 2 * lane;

    if (st_on) {
        const float* s0 = encb + s_off;
        uint32_t d0 = smb + OFF_BUF0 + d_off;
        #pragma unroll
        for (int i = 0; i < 16; i++)
            CP_ASYNC8(d0 + i * (8 * RS * 4), s0 + (size_t)i * 8 * tok_stride);
    }
    CP_COMMIT();

    float lw = 0.0f;
    ULL ctx2 = 0ull;
    const int nbn = (wc == 0) ? 4 : 3;
    const uint32_t bfb = smb + OFF_BFRAG + (uint32_t)wc * 1024;  // wc1 -> +256 u32

    #pragma unroll 1
    for (int tt = 0; tt < NTILE; tt++) {
        const int par = tt & 1;
        __syncthreads();   // all reads of buf[(tt+1)&1] from iter tt-1 done

        int mkv = 1;
        if (lane < 16)
            mkv = mask[(size_t)b * Sc + tt * TT + (wid << 4) + lane];

        // ---- prefetch tile tt+1 into the other buffer ----
        if (tt + 1 < NTILE && st_on) {
            const float* sn = encb + (size_t)(tt + 1) * TT * tok_stride + s_off;
            uint32_t dn = smb + (par ? OFF_BUF0 : OFF_BUF1) + d_off;
            #pragma unroll
            for (int i = 0; i < 16; i++)
                CP_ASYNC8(dn + i * (8 * RS * 4), sn + (size_t)i * 8 * tok_stride);
        }
        CP_COMMIT();
        CP_WAIT1();        // tile tt resident
        __syncthreads();

        const float* buf = (const float*)(smem + (par ? OFF_BUF1 : OFF_BUF0));
        const float* pA0 = buf + (wr * 32 + g) * RS + c;

        // ---- GEMM: warp = 32 tokens x (32 or 24) n ----
        float C[2][4][4];
        #pragma unroll
        for (int mt = 0; mt < 2; mt++)
            #pragma unroll
            for (int nb = 0; nb < 4; nb++)
                #pragma unroll
                for (int q = 0; q < 4; q++) C[mt][nb][q] = 0.0f;

        #pragma unroll
        for (int s = 0; s < 7; s++) {
            uint32_t A[2][4];
            #pragma unroll
            for (int mt = 0; mt < 2; mt++) {
                const float* p = pA0 + mt * (16 * RS) + 8 * s;
                A[mt][0] = __float_as_uint(p[0]);
                A[mt][1] = __float_as_uint(p[8 * RS]);
                A[mt][2] = __float_as_uint(p[4]);
                A[mt][3] = __float_as_uint(p[8 * RS + 4]);
            }
            uint4 v0; uint2 v1w1; uint4 v1w0;
            asm("ld.shared.v4.u32 {%0,%1,%2,%3}, [%4];"
                : "=r"(v0.x), "=r"(v0.y), "=r"(v0.z), "=r"(v0.w)
                : "r"(bfb + (uint32_t)(s * 448 + lane * 4) * 4u));
            if (wc == 0) {
                asm("ld.shared.v4.u32 {%0,%1,%2,%3}, [%4];"
                    : "=r"(v1w0.x), "=r"(v1w0.y), "=r"(v1w0.z), "=r"(v1w0.w)
                    : "r"(bfb + (uint32_t)(s * 448 + 128 + lane * 4) * 4u));
            } else {
                asm("ld.shared.v2.u32 {%0,%1}, [%2];"
                    : "=r"(v1w1.x), "=r"(v1w1.y)
                    : "r"(smb + OFF_BFRAG + (uint32_t)(s * 448 + 384 + lane * 2) * 4u));
            }
            MMA_TF32(C[0][0], A[0], v0.x, v0.y);
            MMA_TF32(C[1][0], A[1], v0.x, v0.y);
            MMA_TF32(C[0][1], A[0], v0.z, v0.w);
            MMA_TF32(C[1][1], A[1], v0.z, v0.w);
            if (wc == 0) {
                MMA_TF32(C[0][2], A[0], v1w0.x, v1w0.y);
                MMA_TF32(C[1][2], A[1], v1w0.x, v1w0.y);
                MMA_TF32(C[0][3], A[0], v1w0.z, v1w0.w);
                MMA_TF32(C[1][3], A[1], v1w0.z, v1w0.w);
            } else {
                MMA_TF32(C[0][2], A[0], v1w1.x, v1w1.y);
                MMA_TF32(C[1][2], A[1], v1w1.x, v1w1.y);
            }
        }

        // ---- epilogue: part = sum_n ws[n] * tanh(D) ----
        float part[4] = {0.0f, 0.0f, 0.0f, 0.0f};
        #pragma unroll
        for (int mt = 0; mt < 2; mt++)
            #pragma unroll
            for (int nb = 0; nb < 4; nb++) {
                if (nb >= nbn) continue;
                #pragma unroll
                for (int hi = 0; hi < 2; hi++) {
                    part[mt*2+hi] = fmaf(wsr[nb][0], fast_tanh(C[mt][nb][hi*2]),   part[mt*2+hi]);
                    part[mt*2+hi] = fmaf(wsr[nb][1], fast_tanh(C[mt][nb][hi*2+1]), part[mt*2+hi]);
                }
            }
        #pragma unroll
        for (int q = 0; q < 4; q++) {
            part[q] += __shfl_xor_sync(0xffffffffu, part[q], 1);
            part[q] += __shfl_xor_sync(0xffffffffu, part[q], 2);
        }
        if (c == 0) {
            #pragma unroll
            for (int mt = 0; mt < 2; mt++)
                #pragma unroll
                for (int hi = 0; hi < 2; hi++)
                    spart[wc * TT + wr * 32 + mt * 16 + hi * 8 + g] = part[mt*2+hi];
        }
        __syncthreads();

        // ---- exp in-lane (lane<16 holds token wid*16+lane), then context ----
        float pv = 0.0f;
        if (lane < 16) {
            int t = (wid << 4) + lane;
            float sc = spart[t] + spart[TT + t];
            pv = mkv ? fast_ex2(sc * L2E) : 0.0f;
        }
        #pragma unroll 4
        for (int r = 0; r < 16; r++) {
            float p = __shfl_sync(0xffffffffu, pv, r);
            lw += p;
            if (lane < 25) {
                int t = (wid << 4) + r;
                ULL e2 = *reinterpret_cast<const ULL*>(buf + t * RS + 2 * lane);
                FMA2(ctx2, pack2(p, p), e2);
            }
        }
    }

    // ---- finalize (sctx/sl overlay dead buf0) ----
    ULL (*sctx)[25] = (ULL(*)[25])(smem + OFF_SCTX);
    float* sl = (float*)(smem + OFF_SL);
    if (lane == 0) sl[wid] = lw;
    if (lane < 25) sctx[wid][lane] = ctx2;
    __syncthreads();
    if (tid < 25) {
        float sx = 0.0f, sy = 0.0f, lt = 0.0f;
        #pragma unroll
        for (int i = 0; i < 8; i++) {
            float x, y; unpack2(sctx[i][tid], x, y);
            sx += x; sy += y; lt += sl[i];
        }
        float inv = 1.0f / lt;
        float2 o; o.x = sx * inv; o.y = sy * inv;
        *reinterpret_cast<float2*>(out + (size_t)b * Hc + 2 * tid) = o;
    }
}

extern "C" void kernel_launch(void* const* d_in, const int* in_sizes, int n_in,
                              void* d_out, int out_size) {
    const float* dec  = (const float*)d_in[0];
    const float* enc  = (const float*)d_in[1];
    const int*   mask = (const int*)  d_in[2];
    const float* Wp   = (const float*)d_in[3];
    const float* We   = (const float*)d_in[4];
    const float* Ws   = (const float*)d_in[5];
    float* out = (float*)d_out;

    cudaFuncSetAttribute(additive_attn_kernel,
                         cudaFuncAttributeMaxDynamicSharedMemorySize, SMEM_BYTES);
    additive_attn_kernel<<<Bc, NTH, SMEM_BYTES>>>(dec, enc, mask, Wp, We, Ws, out);
}

// round 9
// speedup vs baseline: 1.1866x; 1.1866x over previous
#include <cuda_runtime.h>
#include <math_constants.h>
#include <cstdint>

typedef unsigned long long ULL;

#define Bc 1024
#define Sc 2048
#define Hc 50
#define TT 128
#define NTILE 16
#define NTH 256
#define RS 60
#define L2E 1.4426950408889634f

// ---- dynamic SMEM layout (bytes), total 93440 -> 2 CTAs/SM ----
#define OFF_BUF0  0                 // float[128*60] 30720
#define OFF_BUF1  30720             // float[128*60] 30720
#define OFF_BUF2  61440             // float[128*60] 30720 (transient bfrag at setup)
#define OFF_WS    92160             // float[64]       256
#define OFF_SPART 92416             // float[2*128]   1024
#define SMEM_BYTES 93440
#define OFF_PPV   OFF_SPART         // overlay: setup only
#define OFF_SCTX  0                 // overlay buf0: post-loop only
#define OFF_SL    1600

__device__ __forceinline__ uint32_t smem_u32(const void* p) {
    uint32_t a;
    asm("{ .reg .u64 t; cvta.to.shared.u64 t, %1; cvt.u32.u64 %0, t; }" : "=r"(a) : "l"(p));
    return a;
}
__device__ __forceinline__ float fast_ex2(float x) {
    float r; asm("ex2.approx.f32 %0, %1;" : "=f"(r) : "f"(x)); return r;
}
__device__ __forceinline__ float fast_tanh(float x) {
    float r; asm("tanh.approx.f32 %0, %1;" : "=f"(r) : "f"(x)); return r;
}
__device__ __forceinline__ ULL pack2(float lo, float hi) {
    ULL r; asm("mov.b64 %0, {%1, %2};" : "=l"(r) : "f"(lo), "f"(hi)); return r;
}
__device__ __forceinline__ void unpack2(ULL v, float& lo, float& hi) {
    asm("mov.b64 {%0, %1}, %2;" : "=f"(lo), "=f"(hi) : "l"(v));
}
#define FMA2(d, a, b) asm("fma.rn.f32x2 %0, %1, %2, %0;" : "+l"(d) : "l"(a), "l"(b))
__device__ __forceinline__ ULL add2(ULL a, ULL b) {
    ULL r; asm("add.rn.f32x2 %0, %1, %2;" : "=l"(r) : "l"(a), "l"(b)); return r;
}
__device__ __forceinline__ uint32_t to_tf32(float v) {
    uint32_t u; asm("cvt.rna.tf32.f32 %0, %1;" : "=r"(u) : "f"(v)); return u;
}

#define MMA_TF32(C, A, B0, B1)                                                  \
    asm("mma.sync.aligned.m16n8k8.row.col.f32.tf32.tf32.f32 "                   \
        "{%0,%1,%2,%3}, {%4,%5,%6,%7}, {%8,%9}, {%0,%1,%2,%3};"                 \
        : "+f"((C)[0]), "+f"((C)[1]), "+f"((C)[2]), "+f"((C)[3])                \
        : "r"((A)[0]), "r"((A)[1]), "r"((A)[2]), "r"((A)[3]), "r"(B0), "r"(B1))

#define CP_ASYNC8(dst, src) \
    asm volatile("cp.async.ca.shared.global [%0], [%1], 8;" :: "r"(dst), "l"(src))
#define CP_COMMIT() asm volatile("cp.async.commit_group;" ::: "memory")
#define CP_WAIT1()  asm volatile("cp.async.wait_group 1;" ::: "memory")

__global__ __launch_bounds__(NTH, 2)
void additive_attn_kernel(const float* __restrict__ dec,
                          const float* __restrict__ enc,     // (S,B,H)
                          const int*   __restrict__ mask,    // (B,S)
                          const float* __restrict__ Wp,
                          const float* __restrict__ We,
                          const float* __restrict__ Ws,
                          float* __restrict__ out)
{
    extern __shared__ __align__(16) char smem[];
    const uint32_t smb = smem_u32(smem);
    float* ws    = (float*)(smem + OFF_WS);
    float* ppv   = (float*)(smem + OFF_PPV);
    float* spart = (float*)(smem + OFF_SPART);

    const int b    = blockIdx.x;
    const int tid  = threadIdx.x;
    const int lane = tid & 31;
    const int wid  = tid >> 5;
    const int g    = lane >> 2;
    const int c    = lane & 3;
    const int wr   = wid & 3;      // token block (32 tokens)
    const int wc   = wid >> 2;     // n half

    // ---- setup: pp, ws ----
    if (tid < 64) {
        float pp = 0.0f;
        if (tid < Hc) {
            #pragma unroll
            for (int k = 0; k < Hc; k++)
                pp = fmaf(Wp[tid * Hc + k], dec[b * Hc + k], pp);
        }
        ppv[tid] = pp;
        ws[tid]  = (tid < Hc) ? Ws[tid] : 0.0f;
    }
    __syncthreads();

    // ---- build B fragments (fragment-major, tf32) in transient BUF2 region ----
    uint32_t* bfrag = (uint32_t*)(smem + OFF_BUF2);
    for (int i = tid; i < 7 * 8 * 32 * 2; i += NTH) {
        int r  = i & 1;
        int ln = (i >> 1) & 31;
        int nb = (i >> 6) & 7;
        int s  = i >> 9;
        int k  = 8 * s + (ln & 3) + 4 * r;
        int n  = nb * 8 + (ln >> 2);
        float v = 0.0f;
        if (n < Hc) {
            if (k < Hc)       v = We[n * Hc + k];
            else if (k == 50) v = ppv[n];
        }
        bfrag[i] = to_tf32(v);
    }
    __syncthreads();

    // ---- hoist B frags + ws to registers ----
    uint2 Breg[7][4];
    #pragma unroll
    for (int s = 0; s < 7; s++)
        #pragma unroll
        for (int nb = 0; nb < 4; nb++)
            Breg[s][nb] = *reinterpret_cast<const uint2*>(
                bfrag + s * 512 + (wc * 4 + nb) * 64 + lane * 2);
    float wsr[4][2];
    #pragma unroll
    for (int nb = 0; nb < 4; nb++) {
        wsr[nb][0] = ws[wc * 32 + nb * 8 + 2 * c];
        wsr[nb][1] = ws[wc * 32 + nb * 8 + 2 * c + 1];
    }
    __syncthreads();   // bfrag consumed; BUF2 free

    // ---- pad cols 50..59 in ALL THREE buffers ----
    for (int i = tid; i < TT * 10; i += NTH) {
        int t = i / 10, cc = i - 10 * (i / 10);
        float v = (cc == 0) ? 1.0f : 0.0f;          // col 50 = 1.0 (pp lane)
        ((float*)(smem + OFF_BUF0))[t * RS + 50 + cc] = v;
        ((float*)(smem + OFF_BUF1))[t * RS + 50 + cc] = v;
        ((float*)(smem + OFF_BUF2))[t * RS + 50 + cc] = v;
    }

    // ---- staging geometry: lane = 8B chunk (0..24), token = wid + 8i ----
    const float* encb = enc + (size_t)b * Hc;
    const bool st_on = (lane < 25);
    const size_t tok_stride = (size_t)(Bc * Hc);
    const uint32_t d_off = (uint32_t)(wid * RS + 2 * lane) * 4u;
    const size_t  s_off = (size_t)wid * tok_stride + 2 * lane;

    // ---- prologue: prefetch tiles 0 and 1 ----
    if (st_on) {
        const float* s0 = encb + s_off;
        #pragma unroll
        for (int i = 0; i < 16; i++)
            CP_ASYNC8(smb + OFF_BUF0 + d_off + i * (8 * RS * 4),
                      s0 + (size_t)i * 8 * tok_stride);
    }
    CP_COMMIT();
    if (st_on) {
        const float* s1 = encb + (size_t)TT * tok_stride + s_off;
        #pragma unroll
        for (int i = 0; i < 16; i++)
            CP_ASYNC8(smb + OFF_BUF1 + d_off + i * (8 * RS * 4),
                      s1 + (size_t)i * 8 * tok_stride);
    }
    CP_COMMIT();

    float lwA = 0.0f, lwB = 0.0f;
    ULL ctxA = 0ull, ctxB = 0ull;
    const bool skip_nb3 = (wc == 1);   // n 56..63 all have ws == 0

    uint32_t oCur = OFF_BUF0, oNxt = OFF_BUF1, oNx2 = OFF_BUF2;

    #pragma unroll 1
    for (int tt = 0; tt < NTILE; tt++) {
        int mkv = 1;
        if (lane < 16)
            mkv = mask[(size_t)b * Sc + tt * TT + (wid << 4) + lane];

        CP_WAIT1();        // tile tt resident
        __syncthreads();   // visible to all; also orders reuse of oNx2

        const float* buf = (const float*)(smem + oCur);
        const float* pA0 = buf + (wr * 32 + g) * RS + c;

        // ---- prefetch tile tt+2 into oNx2 ----
        if (tt + 2 < NTILE && st_on) {
            const float* sn = encb + (size_t)(tt + 2) * TT * tok_stride + s_off;
            uint32_t dn = smb + oNx2 + d_off;
            #pragma unroll
            for (int i = 0; i < 16; i++)
                CP_ASYNC8(dn + i * (8 * RS * 4), sn + (size_t)i * 8 * tok_stride);
        }
        CP_COMMIT();

        // ---- GEMM: warp = 32 tokens x 32 n ----
        float C[2][4][4];
        #pragma unroll
        for (int mt = 0; mt < 2; mt++)
            #pragma unroll
            for (int nb = 0; nb < 4; nb++)
                #pragma unroll
                for (int q = 0; q < 4; q++) C[mt][nb][q] = 0.0f;

        #pragma unroll
        for (int s = 0; s < 7; s++) {
            uint32_t A[2][4];
            #pragma unroll
            for (int mt = 0; mt < 2; mt++) {
                const float* p = pA0 + mt * (16 * RS) + 8 * s;
                A[mt][0] = __float_as_uint(p[0]);
                A[mt][1] = __float_as_uint(p[8 * RS]);
                A[mt][2] = __float_as_uint(p[4]);
                A[mt][3] = __float_as_uint(p[8 * RS + 4]);
            }
            #pragma unroll
            for (int nb = 0; nb < 4; nb++) {
                if (nb == 3 && skip_nb3) continue;
                MMA_TF32(C[0][nb], A[0], Breg[s][nb].x, Breg[s][nb].y);
                MMA_TF32(C[1][nb], A[1], Breg[s][nb].x, Breg[s][nb].y);
            }
        }

        // ---- epilogue: part = sum_n ws[n] * tanh(D) ----
        float part[4] = {0.0f, 0.0f, 0.0f, 0.0f};
        #pragma unroll
        for (int mt = 0; mt < 2; mt++)
            #pragma unroll
            for (int nb = 0; nb < 4; nb++) {
                if (nb == 3 && skip_nb3) continue;
                #pragma unroll
                for (int hi = 0; hi < 2; hi++) {
                    part[mt*2+hi] = fmaf(wsr[nb][0], fast_tanh(C[mt][nb][hi*2]),   part[mt*2+hi]);
                    part[mt*2+hi] = fmaf(wsr[nb][1], fast_tanh(C[mt][nb][hi*2+1]), part[mt*2+hi]);
                }
            }
        #pragma unroll
        for (int q = 0; q < 4; q++) {
            part[q] += __shfl_xor_sync(0xffffffffu, part[q], 1);
            part[q] += __shfl_xor_sync(0xffffffffu, part[q], 2);
        }
        if (c == 0) {
            #pragma unroll
            for (int mt = 0; mt < 2; mt++)
                #pragma unroll
                for (int hi = 0; hi < 2; hi++)
                    spart[wc * TT + wr * 32 + mt * 16 + hi * 8 + g] = part[mt*2+hi];
        }
        __syncthreads();

        // ---- exp in-lane (lane<16 holds token wid*16+lane), then context ----
        float pv = 0.0f;
        if (lane < 16) {
            int t = (wid << 4) + lane;
            float sc = spart[t] + spart[TT + t];
            pv = mkv ? fast_ex2(sc * L2E) : 0.0f;
        }
        const float* crow = buf + (wid << 4) * RS + 2 * lane;
        #pragma unroll 2
        for (int r = 0; r < 16; r += 2) {
            float p0 = __shfl_sync(0xffffffffu, pv, r);
            float p1 = __shfl_sync(0xffffffffu, pv, r + 1);
            lwA += p0;
            lwB += p1;
            if (lane < 25) {
                ULL e0 = *reinterpret_cast<const ULL*>(crow + r * RS);
                ULL e1 = *reinterpret_cast<const ULL*>(crow + (r + 1) * RS);
                FMA2(ctxA, pack2(p0, p0), e0);
                FMA2(ctxB, pack2(p1, p1), e1);
            }
        }

        // rotate buffers
        uint32_t t0 = oCur; oCur = oNxt; oNxt = oNx2; oNx2 = t0;
    }

    // ---- finalize (sctx/sl overlay dead buf region) ----
    ULL   ctx2 = add2(ctxA, ctxB);
    float lw   = lwA + lwB;
    ULL (*sctx)[25] = (ULL(*)[25])(smem + OFF_SCTX);
    float* sl = (float*)(smem + OFF_SL);
    __syncthreads();   // context reads of all buffers complete before overlay
    if (lane == 0) sl[wid] = lw;
    if (lane < 25) sctx[wid][lane] = ctx2;
    __syncthreads();
    if (tid < 25) {
        float sx = 0.0f, sy = 0.0f, lt = 0.0f;
        #pragma unroll
        for (int i = 0; i < 8; i++) {
            float x, y; unpack2(sctx[i][tid], x, y);
            sx += x; sy += y; lt += sl[i];
        }
        float inv = 1.0f / lt;
        float2 o; o.x = sx * inv; o.y = sy * inv;
        *reinterpret_cast<float2*>(out + (size_t)b * Hc + 2 * tid) = o;
    }
}

extern "C" void kernel_launch(void* const* d_in, const int* in_sizes, int n_in,
                              void* d_out, int out_size) {
    const float* dec  = (const float*)d_in[0];
    const float* enc  = (const float*)d_in[1];
    const int*   mask = (const int*)  d_in[2];
    const float* Wp   = (const float*)d_in[3];
    const float* We   = (const float*)d_in[4];
    const float* Ws   = (const float*)d_in[5];
    float* out = (float*)d_out;

    cudaFuncSetAttribute(additive_attn_kernel,
                         cudaFuncAttributeMaxDynamicSharedMemorySize, SMEM_BYTES);
    additive_attn_kernel<<<Bc, NTH, SMEM_BYTES>>>(dec, enc, mask, Wp, We, Ws, out);
}

// round 10
// speedup vs baseline: 1.3205x; 1.1128x over previous
#include <cuda_runtime.h>
#include <math_constants.h>
#include <cstdint>

typedef unsigned long long ULL;

#define Bc 1024
#define Sc 2048
#define Hc 50
#define TT 128
#define NSPLIT 2
#define NTILE_CTA (Sc / TT / NSPLIT)   // 8 tiles per CTA
#define NTH 256
#define RS 60
#define L2E 1.4426950408889634f

// ---- workspace (unnormalized partials) ----
__device__ float g_ctx[NSPLIT][Bc][52];
__device__ float g_lw[NSPLIT][Bc];

// ---- dynamic SMEM layout (bytes) ----
#define OFF_BUF0  0                // float[128*60]  30720
#define OFF_BUF1  30720            // float[128*60]  30720 (transient bfrag at setup)
#define OFF_WS    61440            // float[64]
#define OFF_PPV   61696            // float[64]
#define OFF_SPART 61952            // float[2*128]
#define OFF_SL    63488            // float[8]
#define OFF_SCTX  63552            // ULL[8][25]
#define SMEM_BYTES (63552 + 1600)

__device__ __forceinline__ uint32_t smem_u32(const void* p) {
    uint32_t a;
    asm("{ .reg .u64 t; cvta.to.shared.u64 t, %1; cvt.u32.u64 %0, t; }" : "=r"(a) : "l"(p));
    return a;
}
__device__ __forceinline__ float fast_ex2(float x) {
    float r; asm("ex2.approx.f32 %0, %1;" : "=f"(r) : "f"(x)); return r;
}
__device__ __forceinline__ float fast_tanh(float x) {
    float r; asm("tanh.approx.f32 %0, %1;" : "=f"(r) : "f"(x)); return r;
}
__device__ __forceinline__ ULL pack2(float lo, float hi) {
    ULL r; asm("mov.b64 %0, {%1, %2};" : "=l"(r) : "f"(lo), "f"(hi)); return r;
}
__device__ __forceinline__ void unpack2(ULL v, float& lo, float& hi) {
    asm("mov.b64 {%0, %1}, %2;" : "=f"(lo), "=f"(hi) : "l"(v));
}
#define FMA2(d, a, b) asm("fma.rn.f32x2 %0, %1, %2, %0;" : "+l"(d) : "l"(a), "l"(b))
__device__ __forceinline__ uint32_t to_tf32(float v) {
    uint32_t u; asm("cvt.rna.tf32.f32 %0, %1;" : "=r"(u) : "f"(v)); return u;
}

#define MMA_TF32(C, A, B0, B1)                                                  \
    asm("mma.sync.aligned.m16n8k8.row.col.f32.tf32.tf32.f32 "                   \
        "{%0,%1,%2,%3}, {%4,%5,%6,%7}, {%8,%9}, {%0,%1,%2,%3};"                 \
        : "+f"((C)[0]), "+f"((C)[1]), "+f"((C)[2]), "+f"((C)[3])                \
        : "r"((A)[0]), "r"((A)[1]), "r"((A)[2]), "r"((A)[3]), "r"(B0), "r"(B1))

#define CP_ASYNC8(dst, src) \
    asm volatile("cp.async.ca.shared.global [%0], [%1], 8;" :: "r"(dst), "l"(src))
#define CP_COMMIT() asm volatile("cp.async.commit_group;" ::: "memory")
#define CP_WAIT1()  asm volatile("cp.async.wait_group 1;" ::: "memory")

__global__ __launch_bounds__(NTH, 2)
void additive_attn_kernel(const float* __restrict__ dec,
                          const float* __restrict__ enc,     // (S,B,H)
                          const int*   __restrict__ mask,    // (B,S)
                          const float* __restrict__ Wp,
                          const float* __restrict__ We,
                          const float* __restrict__ Ws)
{
    extern __shared__ __align__(16) char smem[];
    const uint32_t smb = smem_u32(smem);
    float* ws    = (float*)(smem + OFF_WS);
    float* ppv   = (float*)(smem + OFF_PPV);
    float* spart = (float*)(smem + OFF_SPART);
    float* sl    = (float*)(smem + OFF_SL);
    ULL (*sctx)[25] = (ULL(*)[25])(smem + OFF_SCTX);

    const int b    = blockIdx.x >> 1;
    const int sp   = blockIdx.x & 1;
    const int tid  = threadIdx.x;
    const int lane = tid & 31;
    const int wid  = tid >> 5;
    const int g    = lane >> 2;
    const int c    = lane & 3;
    const int wr   = wid & 3;      // token block (32 tokens)
    const int wc   = wid >> 2;     // n half

    // ---- setup: pp, ws ----
    if (tid < 64) {
        float pp = 0.0f;
        if (tid < Hc) {
            #pragma unroll
            for (int k = 0; k < Hc; k++)
                pp = fmaf(Wp[tid * Hc + k], dec[b * Hc + k], pp);
        }
        ppv[tid] = pp;
        ws[tid]  = (tid < Hc) ? Ws[tid] : 0.0f;
    }
    __syncthreads();

    // ---- build B fragments (fragment-major, tf32) in transient buf1 region ----
    uint32_t* bfrag = (uint32_t*)(smem + OFF_BUF1);
    for (int i = tid; i < 7 * 8 * 32 * 2; i += NTH) {
        int r  = i & 1;
        int ln = (i >> 1) & 31;
        int nb = (i >> 6) & 7;
        int s  = i >> 9;
        int k  = 8 * s + (ln & 3) + 4 * r;
        int n  = nb * 8 + (ln >> 2);
        float v = 0.0f;
        if (n < Hc) {
            if (k < Hc)       v = We[n * Hc + k];
            else if (k == 50) v = ppv[n];
        }
        bfrag[i] = to_tf32(v);
    }
    __syncthreads();

    // ---- hoist B frags + ws to registers ----
    uint2 Breg[7][4];
    #pragma unroll
    for (int s = 0; s < 7; s++)
        #pragma unroll
        for (int nb = 0; nb < 4; nb++)
            Breg[s][nb] = *reinterpret_cast<const uint2*>(
                bfrag + s * 512 + (wc * 4 + nb) * 64 + lane * 2);
    float wsr[4][2];
    #pragma unroll
    for (int nb = 0; nb < 4; nb++) {
        wsr[nb][0] = ws[wc * 32 + nb * 8 + 2 * c];
        wsr[nb][1] = ws[wc * 32 + nb * 8 + 2 * c + 1];
    }
    __syncthreads();   // done reading bfrag; buf1 free

    // ---- init pad cols 50..59 in BOTH buffers ----
    for (int i = tid; i < TT * 10; i += NTH) {
        int t = i / 10, cc = i - 10 * (i / 10);
        float v = (cc == 0) ? 1.0f : 0.0f;          // col 50 = 1.0 (pp lane)
        ((float*)(smem + OFF_BUF0))[t * RS + 50 + cc] = v;
        ((float*)(smem + OFF_BUF1))[t * RS + 50 + cc] = v;
    }

    // ---- staging geometry: lane = 8B chunk (0..24), token = wid + 8i ----
    const float* encb = enc + (size_t)(sp * (Sc / NSPLIT)) * (size_t)(Bc * Hc)
                            + (size_t)b * Hc;
    const int   mbase = sp * (Sc / NSPLIT);
    const bool st_on = (lane < 25);
    const size_t tok_stride = (size_t)(Bc * Hc);
    const uint32_t d_off = (uint32_t)(wid * RS + 2 * lane) * 4u;
    const size_t  s_off = (size_t)wid * tok_stride + 2 * lane;

    // ---- prologue: prefetch tile 0 into buf0 ----
    if (st_on) {
        const float* s0 = encb + s_off;
        uint32_t d0 = smb + OFF_BUF0 + d_off;
        #pragma unroll
        for (int i = 0; i < 16; i++)
            CP_ASYNC8(d0 + i * (8 * RS * 4), s0 + (size_t)i * 8 * tok_stride);
    }
    CP_COMMIT();

    float lw = 0.0f;
    ULL ctx2 = 0ull;
    const bool skip_nb3 = (wc == 1);   // n 56..63 all have ws == 0

    #pragma unroll 1
    for (int tt = 0; tt < NTILE_CTA; tt++) {
        const int par = tt & 1;
        __syncthreads();   // all reads of buf[(tt+1)&1] from iter tt-1 done

        int mkv = 1;
        if (lane < 16)
            mkv = mask[(size_t)b * Sc + mbase + tt * TT + (wid << 4) + lane];

        // ---- prefetch tile tt+1 into the other buffer ----
        if (tt + 1 < NTILE_CTA && st_on) {
            const float* sn = encb + (size_t)(tt + 1) * TT * tok_stride + s_off;
            uint32_t dn = smb + (par ? OFF_BUF0 : OFF_BUF1) + d_off;
            #pragma unroll
            for (int i = 0; i < 16; i++)
                CP_ASYNC8(dn + i * (8 * RS * 4), sn + (size_t)i * 8 * tok_stride);
        }
        CP_COMMIT();
        CP_WAIT1();        // tile tt resident
        __syncthreads();

        const float* buf = (const float*)(smem + (par ? OFF_BUF1 : OFF_BUF0));
        const float* pA0 = buf + (wr * 32 + g) * RS + c;

        // ---- GEMM: warp = 32 tokens x 32 n ----
        float C[2][4][4];
        #pragma unroll
        for (int mt = 0; mt < 2; mt++)
            #pragma unroll
            for (int nb = 0; nb < 4; nb++)
                #pragma unroll
                for (int q = 0; q < 4; q++) C[mt][nb][q] = 0.0f;

        #pragma unroll
        for (int s = 0; s < 7; s++) {
            uint32_t A[2][4];
            #pragma unroll
            for (int mt = 0; mt < 2; mt++) {
                const float* p = pA0 + mt * (16 * RS) + 8 * s;
                A[mt][0] = __float_as_uint(p[0]);
                A[mt][1] = __float_as_uint(p[8 * RS]);
                A[mt][2] = __float_as_uint(p[4]);
                A[mt][3] = __float_as_uint(p[8 * RS + 4]);
            }
            #pragma unroll
            for (int nb = 0; nb < 4; nb++) {
                if (nb == 3 && skip_nb3) continue;
                MMA_TF32(C[0][nb], A[0], Breg[s][nb].x, Breg[s][nb].y);
                MMA_TF32(C[1][nb], A[1], Breg[s][nb].x, Breg[s][nb].y);
            }
        }

        // ---- epilogue: part = sum_n ws[n] * tanh(D) ----
        float part[4] = {0.0f, 0.0f, 0.0f, 0.0f};
        #pragma unroll
        for (int mt = 0; mt < 2; mt++)
            #pragma unroll
            for (int nb = 0; nb < 4; nb++) {
                if (nb == 3 && skip_nb3) continue;
                #pragma unroll
                for (int hi = 0; hi < 2; hi++) {
                    part[mt*2+hi] = fmaf(wsr[nb][0], fast_tanh(C[mt][nb][hi*2]),   part[mt*2+hi]);
                    part[mt*2+hi] = fmaf(wsr[nb][1], fast_tanh(C[mt][nb][hi*2+1]), part[mt*2+hi]);
                }
            }
        #pragma unroll
        for (int q = 0; q < 4; q++) {
            part[q] += __shfl_xor_sync(0xffffffffu, part[q], 1);
            part[q] += __shfl_xor_sync(0xffffffffu, part[q], 2);
        }
        if (c == 0) {
            #pragma unroll
            for (int mt = 0; mt < 2; mt++)
                #pragma unroll
                for (int hi = 0; hi < 2; hi++)
                    spart[wc * TT + wr * 32 + mt * 16 + hi * 8 + g] = part[mt*2+hi];
        }
        __syncthreads();

        // ---- exp in-lane (lane<16 holds token wid*16+lane), then context ----
        float pv = 0.0f;
        if (lane < 16) {
            int t = (wid << 4) + lane;
            float sc = spart[t] + spart[TT + t];
            pv = mkv ? fast_ex2(sc * L2E) : 0.0f;
        }
        #pragma unroll 4
        for (int r = 0; r < 16; r++) {
            float p = __shfl_sync(0xffffffffu, pv, r);
            lw += p;
            if (lane < 25) {
                int t = (wid << 4) + r;
                ULL e2 = *reinterpret_cast<const ULL*>(buf + t * RS + 2 * lane);
                FMA2(ctx2, pack2(p, p), e2);
            }
        }
    }

    // ---- finalize: write unnormalized partials to workspace ----
    if (lane == 0) sl[wid] = lw;
    if (lane < 25) sctx[wid][lane] = ctx2;
    __syncthreads();
    if (tid < 25) {
        float sx = 0.0f, sy = 0.0f, lt = 0.0f;
        #pragma unroll
        for (int i = 0; i < 8; i++) {
            float x, y; unpack2(sctx[i][tid], x, y);
            sx += x; sy += y; lt += sl[i];
        }
        *reinterpret_cast<float2*>(&g_ctx[sp][b][2 * tid]) = make_float2(sx, sy);
        if (tid == 0) g_lw[sp][b] = lt;
    }
}

__global__ __launch_bounds__(32, 32)
void combine_kernel(float* __restrict__ out)
{
    const int b = blockIdx.x;
    const int t = threadIdx.x;
    __shared__ float inv;
    if (t == 0) inv = 1.0f / (g_lw[0][b] + g_lw[1][b]);
    __syncwarp();
    if (t < 25) {
        float2 c0 = *reinterpret_cast<const float2*>(&g_ctx[0][b][2 * t]);
        float2 c1 = *reinterpret_cast<const float2*>(&g_ctx[1][b][2 * t]);
        float2 o;
        o.x = (c0.x + c1.x) * inv;
        o.y = (c0.y + c1.y) * inv;
        *reinterpret_cast<float2*>(out + (size_t)b * Hc + 2 * t) = o;
    }
}

extern "C" void kernel_launch(void* const* d_in, const int* in_sizes, int n_in,
                              void* d_out, int out_size) {
    const float* dec  = (const float*)d_in[0];
    const float* enc  = (const float*)d_in[1];
    const int*   mask = (const int*)  d_in[2];
    const float* Wp   = (const float*)d_in[3];
    const float* We   = (const float*)d_in[4];
    const float* Ws   = (const float*)d_in[5];
    float* out = (float*)d_out;

    cudaFuncSetAttribute(additive_attn_kernel,
                         cudaFuncAttributeMaxDynamicSharedMemorySize, SMEM_BYTES);
    additive_attn_kernel<<<Bc * NSPLIT, NTH, SMEM_BYTES>>>(dec, enc, mask, Wp, We, Ws);
    combine_kernel<<<Bc, 32>>>(out);
}